// round 1
// baseline (speedup 1.0000x reference)
#include <cuda_runtime.h>
#include <cuda_bf16.h>

// Problem constants
#define Bb    32
#define Ll    4096
#define Cc    128
#define OUTD  257          // 1 delta + 128 probs + 128 amt
#define CL    512          // chunk length (stored steps per block)
#define HALO  512          // warm-up steps; 0.9^512 ~ 4e-25 => exact to fp32 tolerance
#define MAXN  (CL + HALO)  // 1024

#define MOM   0.9f
#define OMM   0.1f

__global__ __launch_bounds__(160, 8)
void mpe_kernel(const float* __restrict__ ts,
                const int*   __restrict__ labels,
                const float* __restrict__ amounts,
                float*       __restrict__ out)
{
    __shared__ uint2 s_la[MAXN];   // .x = label bits, .y = amount bits (LDS.64 per step)
    __shared__ float s_dl[MAXN];   // clipped time deltas

    const int chunk = blockIdx.x;
    const int b     = blockIdx.y;
    const int t0    = chunk * CL;
    const int s0    = (t0 - HALO) > 0 ? (t0 - HALO) : 0;  // window start
    const int N     = t0 + CL - s0;                        // total steps (warm + stored)
    const int warm  = t0 - s0;                             // warm-up steps
    const int tid   = threadIdx.x;

    const float* tsb = ts      + (size_t)b * Ll;
    const int*   lb  = labels  + (size_t)b * Ll;
    const float* ab  = amounts + (size_t)b * Ll;

    // ---- cooperative preload of the window into smem ----
    for (int i = tid; i < N; i += blockDim.x) {
        const int g = s0 + i;
        s_la[i] = make_uint2((unsigned)lb[g], __float_as_uint(ab[g]));
        float d = 0.0f;
        if (g > 0) d = fminf(tsb[g] - tsb[g - 1], 100.0f);
        s_dl[i] = d;
    }
    __syncthreads();

    if (tid < Cc) {
        // ---------------- per-channel probs/amt scan ----------------
        const int c = tid;
        float p, a;
        int i0;
        if (s0 == 0) {
            // exact first-element init: y[0] = x[0]
            const uint2 la0 = s_la[0];
            const bool eq0 = ((int)la0.x == c);
            p = eq0 ? 1.0f : 0.0f;
            a = eq0 ? __uint_as_float(la0.y) : 0.0f;
            i0 = 1;
            if (warm == 0) {
                // chunk 0: element 0 is a stored step
                float* o0 = out + (size_t)(b * Ll) * OUTD;
                o0[1 + c]      = p;
                o0[1 + Cc + c] = __fdividef(a, fmaxf(p, 1e-6f));
            }
        } else {
            p = 0.0f; a = 0.0f; i0 = 0;
        }

        // warm-up (no stores) — init error decays by 0.9^HALO
        #pragma unroll 4
        for (int i = i0; i < warm; i++) {
            const uint2 la = s_la[i];
            const bool eq = ((int)la.x == c);
            p = MOM * p + (eq ? OMM : 0.0f);
            const float av = eq ? __uint_as_float(la.y) : 0.0f;
            a = MOM * a + OMM * av;
        }

        // stored steps
        const int istart = (warm > i0) ? warm : i0;
        float* o = out + (size_t)(b * Ll + (s0 + istart)) * OUTD + 1 + c;
        #pragma unroll 4
        for (int i = istart; i < N; i++) {
            const uint2 la = s_la[i];
            const bool eq = ((int)la.x == c);
            p = MOM * p + (eq ? OMM : 0.0f);
            const float av = eq ? __uint_as_float(la.y) : 0.0f;
            a = MOM * a + OMM * av;
            // probs sum is exactly 1 => skip normalization (error ~1e-6)
            const float amt = __fdividef(a, fmaxf(p, 1e-6f));
            o[0]  = p;
            o[Cc] = amt;
            o += OUTD;
        }
    } else if (tid == Cc) {
        // ---------------- delta scan (scalar per batch) ----------------
        float d = 0.0f;   // delta[0] = 0 => zero-init recurrence is exact from t=0
        #pragma unroll 4
        for (int i = 0; i < warm; i++) {
            d = MOM * d + OMM * s_dl[i];
        }
        float* o = out + (size_t)(b * Ll + t0) * OUTD;
        #pragma unroll 4
        for (int i = warm; i < N; i++) {
            d = MOM * d + OMM * s_dl[i];
            *o = d;
            o += OUTD;
        }
    }
    // threads 129..159 only helped with the preload
}

extern "C" void kernel_launch(void* const* d_in, const int* in_sizes, int n_in,
                              void* d_out, int out_size)
{
    const float* ts      = (const float*)d_in[0];
    const int*   labels  = (const int*)  d_in[1];
    const float* amounts = (const float*)d_in[2];
    float* out = (float*)d_out;

    dim3 grid(Ll / CL, Bb);   // (8, 32) = 256 blocks
    dim3 block(160);
    mpe_kernel<<<grid, block>>>(ts, labels, amounts, out);
}

// round 2
// speedup vs baseline: 1.0850x; 1.0850x over previous
#include <cuda_runtime.h>
#include <cuda_bf16.h>

// Problem constants
#define Bb    32
#define Ll    4096
#define Cc    128
#define OUTD  257          // 1 delta + 128 probs + 128 amt
#define CL    256          // chunk length (stored steps per block)
#define HALO  256          // warm-up steps; 0.9^256 ~ 2e-12 => exact to fp32 tolerance
#define MAXN  (CL + HALO)  // 512

#define MOM   0.9f
#define OMM   0.1f

__global__ __launch_bounds__(160, 8)
void mpe_kernel(const float* __restrict__ ts,
                const int*   __restrict__ labels,
                const float* __restrict__ amounts,
                float*       __restrict__ out)
{
    __shared__ uint2 s_la[MAXN];   // .x = label bits, .y = amount bits (LDS.64 per step)
    __shared__ float s_dl[MAXN];   // clipped time deltas

    const int chunk = blockIdx.x;
    const int b     = blockIdx.y;
    const int t0    = chunk * CL;
    const int s0    = (t0 - HALO) > 0 ? (t0 - HALO) : 0;  // window start
    const int N     = t0 + CL - s0;                        // total steps (warm + stored)
    const int warm  = t0 - s0;                             // warm-up steps
    const int tid   = threadIdx.x;

    const float* tsb = ts      + (size_t)b * Ll;
    const int*   lb  = labels  + (size_t)b * Ll;
    const float* ab  = amounts + (size_t)b * Ll;

    // ---- cooperative preload of the window into smem ----
    for (int i = tid; i < N; i += blockDim.x) {
        const int g = s0 + i;
        s_la[i] = make_uint2((unsigned)lb[g], __float_as_uint(ab[g]));
        float d = 0.0f;
        if (g > 0) d = fminf(tsb[g] - tsb[g - 1], 100.0f);
        s_dl[i] = d;
    }
    __syncthreads();

    if (tid < Cc) {
        // ---------------- per-channel probs/amt scan ----------------
        const int c = tid;
        float p, a;
        int i0;
        if (s0 == 0) {
            // exact first-element init: y[0] = x[0]
            const uint2 la0 = s_la[0];
            const bool eq0 = ((int)la0.x == c);
            p = eq0 ? 1.0f : 0.0f;
            a = eq0 ? __uint_as_float(la0.y) : 0.0f;
            i0 = 1;
            if (warm == 0) {
                // chunk 0: element 0 is a stored step
                float* o0 = out + (size_t)(b * Ll) * OUTD;
                o0[1 + c]      = p;
                o0[1 + Cc + c] = __fdividef(a, fmaxf(p, 1e-6f));
            }
        } else {
            p = 0.0f; a = 0.0f; i0 = 0;
        }

        // warm-up (no stores) — init error decays by 0.9^HALO
        #pragma unroll 8
        for (int i = i0; i < warm; i++) {
            const uint2 la = s_la[i];
            const bool eq = ((int)la.x == c);
            p = MOM * p + (eq ? OMM : 0.0f);
            const float av = eq ? __uint_as_float(la.y) : 0.0f;
            a = MOM * a + OMM * av;
        }

        // stored steps
        const int istart = (warm > i0) ? warm : i0;
        float* o = out + (size_t)(b * Ll + (s0 + istart)) * OUTD + 1 + c;
        #pragma unroll 4
        for (int i = istart; i < N; i++) {
            const uint2 la = s_la[i];
            const bool eq = ((int)la.x == c);
            p = MOM * p + (eq ? OMM : 0.0f);
            const float av = eq ? __uint_as_float(la.y) : 0.0f;
            a = MOM * a + OMM * av;
            // probs sum is exactly 1 => skip normalization (error ~1e-6)
            const float amt = __fdividef(a, fmaxf(p, 1e-6f));
            o[0]  = p;
            o[Cc] = amt;
            o += OUTD;
        }
    } else if (tid == Cc) {
        // ---------------- delta scan (scalar per batch) ----------------
        float d = 0.0f;   // delta[0] = 0 => zero-init recurrence is exact from t=0
        #pragma unroll 8
        for (int i = 0; i < warm; i++) {
            d = MOM * d + OMM * s_dl[i];
        }
        float* o = out + (size_t)(b * Ll + t0) * OUTD;
        #pragma unroll 4
        for (int i = warm; i < N; i++) {
            d = MOM * d + OMM * s_dl[i];
            *o = d;
            o += OUTD;
        }
    }
    // remaining threads only helped with the preload
}

extern "C" void kernel_launch(void* const* d_in, const int* in_sizes, int n_in,
                              void* d_out, int out_size)
{
    const float* ts      = (const float*)d_in[0];
    const int*   labels  = (const int*)  d_in[1];
    const float* amounts = (const float*)d_in[2];
    float* out = (float*)d_out;

    dim3 grid(Ll / CL, Bb);   // (16, 32) = 512 blocks
    dim3 block(160);
    mpe_kernel<<<grid, block>>>(ts, labels, amounts, out);
}

// round 3
// speedup vs baseline: 1.5701x; 1.4472x over previous
#include <cuda_runtime.h>
#include <cuda_bf16.h>
#include <cstdint>

// Problem constants
#define Bb    32
#define Ll    4096
#define Cc    128
#define OUTD  257          // 1 delta + 128 probs + 128 amt
#define CL    256          // stored steps per block
#define HALO  192          // 0.9^192 ~ 1.6e-9 -> below fp32 noise
#define MAXN  (CL + HALO)  // 448
#define TT    8            // rows per staged tile
#define NTILE (CL / TT)    // 32

#define MOM   0.9f
#define OMM   0.1f

__device__ __forceinline__ uint32_t smem_u32(const void* p) {
    uint32_t a;
    asm("{ .reg .u64 t; cvta.to.shared.u64 t, %1; cvt.u32.u64 %0, t; }"
        : "=r"(a) : "l"(p));
    return a;
}

__global__ __launch_bounds__(160, 6)
void mpe_kernel(const float* __restrict__ ts,
                const int*   __restrict__ labels,
                const float* __restrict__ amounts,
                float*       __restrict__ out)
{
    __shared__ uint2 s_la[MAXN];                      // label bits, amount bits
    __shared__ float s_dl[MAXN];                      // clipped deltas
    __shared__ __align__(16) float s_out[2][TT * OUTD]; // staged output rows

    const int chunk = blockIdx.x;
    const int b     = blockIdx.y;
    const int t0    = chunk * CL;
    const int s0    = (t0 - HALO) > 0 ? (t0 - HALO) : 0;
    const int N     = t0 + CL - s0;
    const int warm  = t0 - s0;
    const int tid   = threadIdx.x;

    const float* tsb = ts      + (size_t)b * Ll;
    const int*   lb  = labels  + (size_t)b * Ll;
    const float* ab  = amounts + (size_t)b * Ll;

    // ---- cooperative preload of the window into smem ----
    for (int i = tid; i < N; i += blockDim.x) {
        const int g = s0 + i;
        s_la[i] = make_uint2((unsigned)lb[g], __float_as_uint(ab[g]));
        float d = 0.0f;
        if (g > 0) d = fminf(tsb[g] - tsb[g - 1], 100.0f);
        s_dl[i] = d;
    }
    __syncthreads();

    // ---- per-thread scan state ----
    float p = 0.0f, a = 0.0f, dcar = 0.0f;
    const int c = tid;   // channel for tid < Cc
    if (s0 == 0 && tid < Cc) {
        // Carry-init trick: setting carry = x0 makes the i=0 update emit
        // exactly x0 (0.9*x0 + 0.1*x0), so chunk 0 needs no special case.
        const uint2 la0 = s_la[0];
        const bool eq0 = ((int)la0.x == c);
        p = eq0 ? 1.0f : 0.0f;
        a = eq0 ? __uint_as_float(la0.y) : 0.0f;
    }
    // delta: dcar = 0 works for chunk 0 too (dl[0] == 0)

    // ---- warm-up (no stores); init error decays by 0.9^HALO ----
    if (tid < Cc) {
        #pragma unroll 8
        for (int i = 0; i < warm; i++) {
            const uint2 la = s_la[i];
            const bool eq = ((int)la.x == c);
            p = MOM * p + (eq ? OMM : 0.0f);
            a = MOM * a + (eq ? OMM * __uint_as_float(la.y) : 0.0f);
        }
    } else if (tid == Cc) {
        #pragma unroll 8
        for (int i = 0; i < warm; i++)
            dcar = MOM * dcar + OMM * s_dl[i];
    }

    // ---- stored steps: scan into smem tiles, drain via cp.async.bulk ----
    const char* gbase = (const char*)(out + (size_t)(b * Ll + t0) * OUTD);
    int pb = 0;
    for (int tile = 0; tile < NTILE; tile++) {
        float* ob = s_out[pb];
        const int base = warm + tile * TT;

        if (tid < Cc) {
            const uint2* la = s_la + base;
            #pragma unroll
            for (int j = 0; j < TT; j++) {
                const uint2 v = la[j];
                const bool eq = ((int)v.x == c);
                p = MOM * p + (eq ? OMM : 0.0f);
                a = MOM * a + (eq ? OMM * __uint_as_float(v.y) : 0.0f);
                ob[j * OUTD + 1 + c]      = p;                              // probs (sum==1, skip norm)
                ob[j * OUTD + 1 + Cc + c] = __fdividef(a, fmaxf(p, 1e-6f)); // amt
            }
        } else if (tid == Cc) {
            const float* dl = s_dl + base;
            #pragma unroll
            for (int j = 0; j < TT; j++) {
                dcar = MOM * dcar + OMM * dl[j];
                ob[j * OUTD] = dcar;
            }
        }
        __syncthreads();   // tile fully written

        if (tid == Cc + 1) {
            // order generic STS before async-proxy read, then bulk copy the tile
            asm volatile("fence.proxy.async.shared::cta;" ::: "memory");
            const uint64_t gdst = (uint64_t)(gbase + (size_t)tile * TT * OUTD * 4);
            const uint32_t ssrc = smem_u32(ob);
            asm volatile("cp.async.bulk.global.shared::cta.bulk_group [%0], [%1], %2;"
                         :: "l"(gdst), "r"(ssrc), "r"((uint32_t)(TT * OUTD * 4))
                         : "memory");
            asm volatile("cp.async.bulk.commit_group;" ::: "memory");
            // allow 1 copy in flight; guarantees the other buffer is drained
            asm volatile("cp.async.bulk.wait_group 1;" ::: "memory");
        }
        __syncthreads();   // other buffer free for reuse
        pb ^= 1;
    }

    if (tid == Cc + 1)
        asm volatile("cp.async.bulk.wait_group 0;" ::: "memory");
}

extern "C" void kernel_launch(void* const* d_in, const int* in_sizes, int n_in,
                              void* d_out, int out_size)
{
    const float* ts      = (const float*)d_in[0];
    const int*   labels  = (const int*)  d_in[1];
    const float* amounts = (const float*)d_in[2];
    float* out = (float*)d_out;

    dim3 grid(Ll / CL, Bb);   // (16, 32) = 512 blocks
    dim3 block(160);
    mpe_kernel<<<grid, block>>>(ts, labels, amounts, out);
}